// round 1
// baseline (speedup 1.0000x reference)
#include <cuda_runtime.h>
#include <math.h>

#define BB 4
#define CC 64
#define MH 18
#define HH 128
#define WW 128
#define NN 9
#define HWX (HH*WW)

// ---------------- scratch (static __device__, no allocations) ----------------
__device__ float g_update[BB*MH*HH*WW];           // sigmoid(upd conv)
__device__ float g_rgoff [BB*MH*HH*WW];           // pre_offset * sigmoid(rst conv)
__device__ float g_m     [BB*NN*HH*WW];           // sigmoid(wg conv)
__device__ float g_xT    [BB*130*130*CC];         // padded NHWC x_t

__device__ __forceinline__ float sigf(float x) { return 1.f/(1.f + __expf(-x)); }

// ---------------- kernel: zero padded NHWC buffer ----------------
__global__ void k_zero() {
    int i = blockIdx.x * blockDim.x + threadIdx.x;
    const int n = BB*130*130*CC/4;
    if (i < n) reinterpret_cast<float4*>(g_xT)[i] = make_float4(0.f,0.f,0.f,0.f);
}

// ---------------- kernel: NCHW -> padded NHWC transpose ----------------
// grid (4 jblocks, 128 rows, 4 batch), block (32,8)
__global__ void k_pad(const float* __restrict__ x) {
    __shared__ float sm[64][33];
    int jb = blockIdx.x, i0 = blockIdx.y, b = blockIdx.z;
    int tx = threadIdx.x, ty = threadIdx.y;
    int jcol = jb*32 + tx;
    for (int c = ty; c < 64; c += 8)
        sm[c][tx] = x[((b*CC + c)*HH + i0)*WW + jcol];
    __syncthreads();
    for (int jj = ty; jj < 32; jj += 8) {
        int base = ((b*130 + (i0+1))*130 + (jb*32 + jj + 1))*64;
        g_xT[base + tx]      = sm[tx][jj];
        g_xT[base + 32 + tx] = sm[32 + tx][jj];
    }
}

// ---------------- kernel: fused gate convs (upd, rst, wg) ----------------
// tile 16h x 32w, 256 threads, 2 pixels/thread. smem: weights 31752 + input 1224 floats.
#define GATE_SW   (2*18*82*9)          /* 26568 : upd then rst */
#define GATE_SWM  (9*64*9)             /* 5184  : wg           */
#define GATE_SMEMF (GATE_SW + GATE_SWM + 2*18*34)

__global__ void __launch_bounds__(256) k_gatesm(
    const float* __restrict__ x, const float* __restrict__ pre,
    const float* __restrict__ uw, const float* __restrict__ ub,
    const float* __restrict__ rw, const float* __restrict__ rb,
    const float* __restrict__ ww, const float* __restrict__ wb)
{
    extern __shared__ float sh[];
    float* s_w  = sh;                       // [36][82][9] then [9][64][9]
    float* s_in = sh + GATE_SW + GATE_SWM;  // [2][18][34]
    int t  = threadIdx.x;
    int b  = blockIdx.z;
    int h0 = blockIdx.y * 16, w0 = blockIdx.x * 32;

    for (int i = t; i < 13284; i += 256) { s_w[i] = uw[i]; s_w[13284 + i] = rw[i]; }
    for (int i = t; i < 5184;  i += 256) s_w[26568 + i] = ww[i];

    float acc0[36], acc1[36], am0[9], am1[9];
    #pragma unroll
    for (int i = 0; i < 36; ++i) { acc0[i] = 0.f; acc1[i] = 0.f; }
    #pragma unroll
    for (int i = 0; i < 9; ++i)  { am0[i] = 0.f;  am1[i] = 0.f; }

    int ty = t >> 4, tx = t & 15;

    #pragma unroll 1
    for (int c0 = 0; c0 < 82; c0 += 2) {
        __syncthreads();
        for (int e = t; e < 2*18*34; e += 256) {
            int ch = e / 612; int rr = (e % 612) / 34; int cc2 = e % 34;
            int gh = h0 - 1 + rr, gw = w0 - 1 + cc2;
            float v = 0.f;
            if (gh >= 0 && gh < HH && gw >= 0 && gw < WW) {
                int ic = c0 + ch;
                v = (ic < 64) ? x[((b*CC + ic)*HH + gh)*WW + gw]
                              : pre[((b*MH + (ic - 64))*HH + gh)*WW + gw];
            }
            s_in[e] = v;
        }
        __syncthreads();
        #pragma unroll
        for (int ch = 0; ch < 2; ++ch) {
            int ic = c0 + ch;
            #pragma unroll
            for (int ki = 0; ki < 3; ++ki)
            #pragma unroll
            for (int kj = 0; kj < 3; ++kj) {
                float v0 = s_in[ch*612 + (ty + ki)*34 + tx + kj];
                float v1 = s_in[ch*612 + (ty + ki)*34 + tx + 16 + kj];
                int bofs = ic*9 + ki*3 + kj;
                #pragma unroll
                for (int oc = 0; oc < 36; ++oc) {
                    float wv = s_w[oc*738 + bofs];
                    acc0[oc] += v0*wv; acc1[oc] += v1*wv;
                }
                if (ic < 64) {
                    int bm = 26568 + ic*9 + ki*3 + kj;
                    #pragma unroll
                    for (int oc = 0; oc < 9; ++oc) {
                        float wv = s_w[bm + oc*576];
                        am0[oc] += v0*wv; am1[oc] += v1*wv;
                    }
                }
            }
        }
    }

    int h = h0 + ty;
    int w1 = w0 + tx;
    #pragma unroll
    for (int oc = 0; oc < 18; ++oc) {
        int i1 = ((b*MH + oc)*HH + h)*WW + w1;
        int i2 = i1 + 16;
        g_update[i1] = sigf(acc0[oc] + ub[oc]);
        g_update[i2] = sigf(acc1[oc] + ub[oc]);
        float r0 = sigf(acc0[18 + oc] + rb[oc]);
        float r1 = sigf(acc1[18 + oc] + rb[oc]);
        g_rgoff[i1] = pre[i1]*r0;
        g_rgoff[i2] = pre[i2]*r1;
    }
    #pragma unroll
    for (int oc = 0; oc < 9; ++oc) {
        int i1 = ((b*NN + oc)*HH + h)*WW + w1;
        g_m[i1]      = sigf(am0[oc] + wb[oc]);
        g_m[i1 + 16] = sigf(am1[oc] + wb[oc]);
    }
}

// ---------------- kernel: candidate conv + GRU combine ----------------
#define CAND_SW (18*82*9)          /* 13284 */
#define CAND_SMEMF (CAND_SW + 2*18*34)

__global__ void __launch_bounds__(256) k_cand(
    const float* __restrict__ x, const float* __restrict__ pre,
    const float* __restrict__ mean,
    const float* __restrict__ ow, const float* __restrict__ ob,
    float* __restrict__ out_off, float* __restrict__ out_mean)
{
    extern __shared__ float sh[];
    float* s_w  = sh;
    float* s_in = sh + CAND_SW;
    int t  = threadIdx.x;
    int b  = blockIdx.z;
    int h0 = blockIdx.y * 16, w0 = blockIdx.x * 32;

    for (int i = t; i < 13284; i += 256) s_w[i] = ow[i];

    float acc0[18], acc1[18];
    #pragma unroll
    for (int i = 0; i < 18; ++i) { acc0[i] = 0.f; acc1[i] = 0.f; }

    int ty = t >> 4, tx = t & 15;

    #pragma unroll 1
    for (int c0 = 0; c0 < 82; c0 += 2) {
        __syncthreads();
        for (int e = t; e < 2*18*34; e += 256) {
            int ch = e / 612; int rr = (e % 612) / 34; int cc2 = e % 34;
            int gh = h0 - 1 + rr, gw = w0 - 1 + cc2;
            float v = 0.f;
            if (gh >= 0 && gh < HH && gw >= 0 && gw < WW) {
                int ic = c0 + ch;
                v = (ic < 64) ? x[((b*CC + ic)*HH + gh)*WW + gw]
                              : g_rgoff[((b*MH + (ic - 64))*HH + gh)*WW + gw];
            }
            s_in[e] = v;
        }
        __syncthreads();
        #pragma unroll
        for (int ch = 0; ch < 2; ++ch) {
            int ic = c0 + ch;
            #pragma unroll
            for (int ki = 0; ki < 3; ++ki)
            #pragma unroll
            for (int kj = 0; kj < 3; ++kj) {
                float v0 = s_in[ch*612 + (ty + ki)*34 + tx + kj];
                float v1 = s_in[ch*612 + (ty + ki)*34 + tx + 16 + kj];
                int bofs = ic*9 + ki*3 + kj;
                #pragma unroll
                for (int oc = 0; oc < 18; ++oc) {
                    float wv = s_w[oc*738 + bofs];
                    acc0[oc] += v0*wv; acc1[oc] += v1*wv;
                }
            }
        }
    }

    int h = h0 + ty;
    int w1 = w0 + tx;
    #pragma unroll
    for (int oc = 0; oc < 18; ++oc) {
        int i1 = ((b*MH + oc)*HH + h)*WW + w1;
        int i2 = i1 + 16;
        float c0v = tanhf(acc0[oc] + ob[oc]);
        float c1v = tanhf(acc1[oc] + ob[oc]);
        float u0 = g_update[i1], u1 = g_update[i2];
        float p0 = pre[i1], p1 = pre[i2];
        float mn0 = 0.5f*(mean[i1] + p0);
        float mn1 = 0.5f*(mean[i2] + p1);
        out_off[i1]  = p0*(1.f - u0) + c0v*u0 + mn0;
        out_off[i2]  = p1*(1.f - u1) + c1v*u1 + mn1;
        out_mean[i1] = mn0;
        out_mean[i2] = mn1;
    }
}

// ---------------- kernel: deformable warp + regroup conv ----------------
// Persistent blocks. smem: W [64][577] (padded) + v [64][65].
#define WARP_SWF (64*577)
#define WARP_SVF (64*65)
#define WARP_SMEMF (WARP_SWF + WARP_SVF)

__global__ void __launch_bounds__(256) k_warp(
    const float* __restrict__ off, const float* __restrict__ Wc,
    float* __restrict__ out)
{
    extern __shared__ float sh[];
    float* sW = sh;
    float* sv = sh + WARP_SWF;
    int t = threadIdx.x;
    int lane = t & 31, warp = t >> 5;

    for (int i = t; i < 64*576; i += 256) {
        int co = i / 576, k = i % 576;
        sW[co*577 + k] = Wc[i];
    }
    __syncthreads();

    int co_base = t & 15;   // co = co_base + 16*i
    int pg = t >> 4;        // pix = pg*4 + j

    for (int g = blockIdx.x; g < BB*HH*2; g += gridDim.x) {
        int b = g >> 8;
        int rem = g & 255;
        int h  = rem >> 1;
        int w0 = (rem & 1) << 6;

        float acc[4][4];
        #pragma unroll
        for (int i = 0; i < 4; ++i)
            #pragma unroll
            for (int j = 0; j < 4; ++j) acc[i][j] = 0.f;

        #pragma unroll 1
        for (int n = 0; n < 9; ++n) {
            float pnx = (float)(n/3 - 1), pny = (float)(n%3 - 1);
            // gather: warp owns pixels warp*8 .. warp*8+7
            #pragma unroll 1
            for (int p = 0; p < 8; ++p) {
                int pix = warp*8 + p;
                int wc  = w0 + pix;
                float ox = off[((b*MH + n     )*HH + h)*WW + wc];
                float oy = off[((b*MH + 9 + n )*HH + h)*WW + wc];
                float mm = g_m[((b*NN + n)*HH + h)*WW + wc];
                float px = (float)(h + 1) + pnx + ox;
                float py = (float)(wc + 1) + pny + oy;
                float fx = floorf(px), fy = floorf(py);
                float qxl = fminf(fmaxf(fx,       0.f), 129.f);
                float qxr = fminf(fmaxf(fx + 1.f, 0.f), 129.f);
                float qyl = fminf(fmaxf(fy,       0.f), 129.f);
                float qyr = fminf(fmaxf(fy + 1.f, 0.f), 129.f);
                float pxc = fminf(fmaxf(px, 0.f), 129.f);
                float pyc = fminf(fmaxf(py, 0.f), 129.f);
                float gx_l = 1.f + (qxl - pxc);
                float gx_r = 1.f - (qxr - pxc);
                float gy_l = 1.f + (qyl - pyc);
                float gy_r = 1.f - (qyr - pyc);
                float glt = gx_l*gy_l*mm, grb = gx_r*gy_r*mm;
                float glb = gx_l*gy_r*mm, grt = gx_r*gy_l*mm;
                int ixl = (int)qxl, ixr = (int)qxr, iyl = (int)qyl, iyr = (int)qyr;
                const float* xb  = g_xT + b*130*130*64;
                const float* plt = xb + (ixl*130 + iyl)*64;
                const float* prb = xb + (ixr*130 + iyr)*64;
                const float* plb = xb + (ixl*130 + iyr)*64;
                const float* prt = xb + (ixr*130 + iyl)*64;
                float v0 = glt*plt[lane]    + grb*prb[lane]    + glb*plb[lane]    + grt*prt[lane];
                float v1 = glt*plt[lane+32] + grb*prb[lane+32] + glb*plb[lane+32] + grt*prt[lane+32];
                sv[pix*65 + lane]      = v0;
                sv[pix*65 + lane + 32] = v1;
            }
            __syncthreads();
            // matmul accumulate: out[co][pix] += W[co][ci*9+n] * v[pix][ci]
            #pragma unroll 4
            for (int ci = 0; ci < 64; ++ci) {
                float wv[4];
                #pragma unroll
                for (int i = 0; i < 4; ++i)
                    wv[i] = sW[(co_base + 16*i)*577 + ci*9 + n];
                #pragma unroll
                for (int j = 0; j < 4; ++j) {
                    float vv = sv[(pg*4 + j)*65 + ci];
                    #pragma unroll
                    for (int i = 0; i < 4; ++i) acc[i][j] += wv[i]*vv;
                }
            }
            __syncthreads();
        }

        // stage outputs to smem then coalesced global write
        #pragma unroll
        for (int i = 0; i < 4; ++i)
            #pragma unroll
            for (int j = 0; j < 4; ++j)
                sv[(pg*4 + j)*65 + co_base + 16*i] = acc[i][j];
        __syncthreads();
        for (int i = t; i < 4096; i += 256) {
            int co = i >> 6, pix = i & 63;
            out[((b*CC + co)*HH + h)*WW + w0 + pix] = sv[pix*65 + co];
        }
        __syncthreads();
    }
}

// ---------------- launch ----------------
extern "C" void kernel_launch(void* const* d_in, const int* in_sizes, int n_in,
                              void* d_out, int out_size)
{
    const float* x    = (const float*)d_in[0];
    const float* pre  = (const float*)d_in[1];
    const float* mean = (const float*)d_in[2];
    const float* uw   = (const float*)d_in[3];
    const float* ub   = (const float*)d_in[4];
    const float* rw   = (const float*)d_in[5];
    const float* rb   = (const float*)d_in[6];
    const float* ow   = (const float*)d_in[7];
    const float* ob   = (const float*)d_in[8];
    const float* ww   = (const float*)d_in[9];
    const float* wb   = (const float*)d_in[10];
    const float* wc   = (const float*)d_in[11];

    float* out_x    = (float*)d_out;
    float* out_off  = out_x + BB*CC*HH*WW;
    float* out_mean = out_off + BB*MH*HH*WW;

    cudaFuncSetAttribute(k_gatesm, cudaFuncAttributeMaxDynamicSharedMemorySize,
                         GATE_SMEMF * (int)sizeof(float));
    cudaFuncSetAttribute(k_cand, cudaFuncAttributeMaxDynamicSharedMemorySize,
                         CAND_SMEMF * (int)sizeof(float));
    cudaFuncSetAttribute(k_warp, cudaFuncAttributeMaxDynamicSharedMemorySize,
                         WARP_SMEMF * (int)sizeof(float));

    k_zero<<<(BB*130*130*CC/4 + 255)/256, 256>>>();
    k_pad<<<dim3(4, 128, 4), dim3(32, 8)>>>(x);

    dim3 gg(WW/32, HH/16, BB);
    k_gatesm<<<gg, 256, GATE_SMEMF * sizeof(float)>>>(x, pre, uw, ub, rw, rb, ww, wb);
    k_cand<<<gg, 256, CAND_SMEMF * sizeof(float)>>>(x, pre, mean, ow, ob, out_off, out_mean);
    k_warp<<<148, 256, WARP_SMEMF * sizeof(float)>>>(out_off, wc, out_x);
}

// round 2
// speedup vs baseline: 1.3970x; 1.3970x over previous
#include <cuda_runtime.h>
#include <math.h>

#define BB 4
#define CC 64
#define MH 18
#define HH 128
#define WW 128
#define NN 9

typedef unsigned long long ull;

// ---------------- scratch (static __device__, no allocations) ----------------
__device__ float g_update[BB*MH*HH*WW];           // sigmoid(upd conv)
__device__ float g_rgoff [BB*MH*HH*WW];           // pre_offset * sigmoid(rst conv)
__device__ float g_m     [BB*NN*HH*WW];           // sigmoid(wg conv)
__device__ float g_xT    [BB*130*130*CC];         // padded NHWC x_t

__device__ __forceinline__ float sigf(float x) { return 1.f/(1.f + __expf(-x)); }

// ---- f32x2 helpers (Blackwell packed fp32) ----
__device__ __forceinline__ ull ffma2(ull a, ull b, ull c) {
    ull d; asm("fma.rn.f32x2 %0,%1,%2,%3;" : "=l"(d) : "l"(a), "l"(b), "l"(c)); return d;
}
__device__ __forceinline__ ull fmul2(ull a, ull b) {
    ull d; asm("mul.rn.f32x2 %0,%1,%2;" : "=l"(d) : "l"(a), "l"(b)); return d;
}
__device__ __forceinline__ ull dup2(float v) {
    ull d; asm("mov.b64 %0,{%1,%1};" : "=l"(d) : "f"(v)); return d;
}
__device__ __forceinline__ void unpack2(ull p, float& lo, float& hi) {
    asm("mov.b64 {%0,%1},%2;" : "=f"(lo), "=f"(hi) : "l"(p));
}

// ---------------- kernel: zero padded NHWC buffer ----------------
__global__ void k_zero() {
    int i = blockIdx.x * blockDim.x + threadIdx.x;
    const int n = BB*130*130*CC/4;
    if (i < n) reinterpret_cast<float4*>(g_xT)[i] = make_float4(0.f,0.f,0.f,0.f);
}

// ---------------- kernel: NCHW -> padded NHWC transpose ----------------
__global__ void k_pad(const float* __restrict__ x) {
    __shared__ float sm[64][33];
    int jb = blockIdx.x, i0 = blockIdx.y, b = blockIdx.z;
    int tx = threadIdx.x, ty = threadIdx.y;
    int jcol = jb*32 + tx;
    for (int c = ty; c < 64; c += 8)
        sm[c][tx] = x[((b*CC + c)*HH + i0)*WW + jcol];
    __syncthreads();
    for (int jj = ty; jj < 32; jj += 8) {
        int base = ((b*130 + (i0+1))*130 + (jb*32 + jj + 1))*64;
        g_xT[base + tx]      = sm[tx][jj];
        g_xT[base + 32 + tx] = sm[32 + tx][jj];
    }
}

// ================= fused gate convs (upd, rst, wg) — f32x2 =================
// tile 16h x 32w, 256 threads, pixel pair (2 adjacent cols) per thread.
// smem weights repacked [ic(82)][k(9)][oc(48 pad)], input double-buffered [2][2*18*34]
#define GOC   48
#define GATE_WF (82*9*GOC)            /* 35424 */
#define IN_TILE (2*18*34)             /* 1224  */
#define GATE_SMEMF (GATE_WF + 2*IN_TILE)

__global__ void __launch_bounds__(256, 1) k_gatesm(
    const float* __restrict__ x, const float* __restrict__ pre,
    const float* __restrict__ uw, const float* __restrict__ ub,
    const float* __restrict__ rw, const float* __restrict__ rb,
    const float* __restrict__ ww, const float* __restrict__ wb)
{
    extern __shared__ float sh[];
    float* s_w  = sh;                 // [82*9][48]
    float* s_in = sh + GATE_WF;       // 2 buffers of [2][18][34]
    int t  = threadIdx.x;
    int b  = blockIdx.z;
    int h0 = blockIdx.y * 16, w0 = blockIdx.x * 32;

    // zero weight smem (pad cols + m rows at ic>=64)
    for (int i = t; i < GATE_WF/4; i += 256)
        reinterpret_cast<float4*>(s_w)[i] = make_float4(0.f,0.f,0.f,0.f);
    __syncthreads();
    // repack: upd -> oc 0..17, rst -> 18..35, wg -> 36..44 (ic<64 only)
    for (int i = t; i < 18*738; i += 256) {
        int oc = i / 738, k = i % 738;
        s_w[k*GOC + oc]      = uw[i];
        s_w[k*GOC + 18 + oc] = rw[i];
    }
    for (int i = t; i < 9*576; i += 256) {
        int oc = i / 576, k = i % 576;
        s_w[k*GOC + 36 + oc] = ww[i];
    }

    ull acc[24][2];
    #pragma unroll
    for (int q = 0; q < 24; ++q) { acc[q][0] = 0ULL; acc[q][1] = 0ULL; }

    int ty  = t >> 4;          // row 0..15
    int txp = (t & 15) * 2;    // col pair base 0..30

    // stage chunk 0
    for (int e = t; e < IN_TILE; e += 256) {
        int ch = e / 612; int rr = (e % 612) / 34; int cc2 = e % 34;
        int gh = h0 - 1 + rr, gw = w0 - 1 + cc2;
        float v = 0.f;
        if (gh >= 0 && gh < HH && gw >= 0 && gw < WW) {
            v = (ch == 0) ? x[((b*CC + 0)*HH + gh)*WW + gw]
                          : x[((b*CC + 1)*HH + gh)*WW + gw];
        }
        s_in[e] = v;
    }
    __syncthreads();

    #pragma unroll 1
    for (int it = 0; it < 41; ++it) {
        int c0 = it*2;
        const float* buf = s_in + (it & 1) * IN_TILE;

        // prefetch next chunk into registers
        float pf[5];
        if (it < 40) {
            int nc0 = c0 + 2;
            #pragma unroll
            for (int s = 0; s < 5; ++s) {
                int e = t + s*256;
                float v = 0.f;
                if (e < IN_TILE) {
                    int ch = e / 612; int rr = (e % 612) / 34; int cc2 = e % 34;
                    int gh = h0 - 1 + rr, gw = w0 - 1 + cc2;
                    if (gh >= 0 && gh < HH && gw >= 0 && gw < WW) {
                        int ic = nc0 + ch;
                        v = (ic < 64) ? x[((b*CC + ic)*HH + gh)*WW + gw]
                                      : pre[((b*MH + (ic - 64))*HH + gh)*WW + gw];
                    }
                }
                pf[s] = v;
            }
        }

        #pragma unroll
        for (int ch = 0; ch < 2; ++ch) {
            int icb = (c0 + ch)*9;
            #pragma unroll
            for (int ki = 0; ki < 3; ++ki) {
                int ibase = ch*612 + (ty + ki)*34 + txp;
                float2 a0 = *reinterpret_cast<const float2*>(buf + ibase);
                float2 a1 = *reinterpret_cast<const float2*>(buf + ibase + 2);
                ull d0 = dup2(a0.x), d1 = dup2(a0.y), d2 = dup2(a1.x), d3 = dup2(a1.y);
                #pragma unroll
                for (int kj = 0; kj < 3; ++kj) {
                    ull dA = (kj == 0) ? d0 : (kj == 1) ? d1 : d2;
                    ull dB = (kj == 0) ? d1 : (kj == 1) ? d2 : d3;
                    const float* wrow = s_w + (icb + ki*3 + kj)*GOC;
                    #pragma unroll
                    for (int q = 0; q < 12; ++q) {
                        ulonglong2 wv = *reinterpret_cast<const ulonglong2*>(wrow + q*4);
                        acc[q*2  ][0] = ffma2(wv.x, dA, acc[q*2  ][0]);
                        acc[q*2  ][1] = ffma2(wv.x, dB, acc[q*2  ][1]);
                        acc[q*2+1][0] = ffma2(wv.y, dA, acc[q*2+1][0]);
                        acc[q*2+1][1] = ffma2(wv.y, dB, acc[q*2+1][1]);
                    }
                }
            }
        }

        if (it < 40) {
            float* nbuf = s_in + ((it + 1) & 1) * IN_TILE;
            #pragma unroll
            for (int s = 0; s < 5; ++s) {
                int e = t + s*256;
                if (e < IN_TILE) nbuf[e] = pf[s];
            }
        }
        __syncthreads();
    }

    int h = h0 + ty;
    int w1 = w0 + txp;
    // upd: oc pairs 0..8 ; rst: 9..17 ; m: 18..22
    #pragma unroll
    for (int op = 0; op < 9; ++op) {
        float uA0, uB0, uA1, uB1;
        unpack2(acc[op][0], uA0, uB0);   // oc=2op: px0 in lo? no: [0] is px0 pair over oc? see below
        unpack2(acc[op][1], uA1, uB1);
        // acc[op][p] holds f32x2 = (oc_even, oc_odd) for pixel p
        int oc0 = 2*op, oc1 = 2*op + 1;
        int i0 = ((b*MH + oc0)*HH + h)*WW + w1;
        int i1 = ((b*MH + oc1)*HH + h)*WW + w1;
        float2 r0 = make_float2(sigf(uA0 + ub[oc0]), sigf(uA1 + ub[oc0]));
        float2 r1 = make_float2(sigf(uB0 + ub[oc1]), sigf(uB1 + ub[oc1]));
        *reinterpret_cast<float2*>(g_update + i0) = r0;
        *reinterpret_cast<float2*>(g_update + i1) = r1;
    }
    #pragma unroll
    for (int op = 9; op < 18; ++op) {
        float uA0, uB0, uA1, uB1;
        unpack2(acc[op][0], uA0, uB0);
        unpack2(acc[op][1], uA1, uB1);
        int oc0 = 2*op - 18, oc1 = oc0 + 1;
        int i0 = ((b*MH + oc0)*HH + h)*WW + w1;
        int i1 = ((b*MH + oc1)*HH + h)*WW + w1;
        float2 p0 = *reinterpret_cast<const float2*>(pre + i0);
        float2 p1 = *reinterpret_cast<const float2*>(pre + i1);
        float2 r0 = make_float2(p0.x * sigf(uA0 + rb[oc0]), p0.y * sigf(uA1 + rb[oc0]));
        float2 r1 = make_float2(p1.x * sigf(uB0 + rb[oc1]), p1.y * sigf(uB1 + rb[oc1]));
        *reinterpret_cast<float2*>(g_rgoff + i0) = r0;
        *reinterpret_cast<float2*>(g_rgoff + i1) = r1;
    }
    #pragma unroll
    for (int op = 18; op < 23; ++op) {
        float uA0, uB0, uA1, uB1;
        unpack2(acc[op][0], uA0, uB0);
        unpack2(acc[op][1], uA1, uB1);
        int oc0 = 2*(op - 18), oc1 = oc0 + 1;
        int i0 = ((b*NN + oc0)*HH + h)*WW + w1;
        float2 r0 = make_float2(sigf(uA0 + wb[oc0]), sigf(uA1 + wb[oc0]));
        *reinterpret_cast<float2*>(g_m + i0) = r0;
        if (oc1 < 9) {
            int i1 = ((b*NN + oc1)*HH + h)*WW + w1;
            float2 r1 = make_float2(sigf(uB0 + wb[oc1]), sigf(uB1 + wb[oc1]));
            *reinterpret_cast<float2*>(g_m + i1) = r1;
        }
    }
}

// ================= candidate conv + GRU combine — f32x2 =================
#define COC 20
#define CAND_WF (82*9*COC)            /* 14760 */
#define CAND_SMEMF (CAND_WF + 2*IN_TILE)

__global__ void __launch_bounds__(256, 1) k_cand(
    const float* __restrict__ x, const float* __restrict__ pre,
    const float* __restrict__ mean,
    const float* __restrict__ ow, const float* __restrict__ ob,
    float* __restrict__ out_off, float* __restrict__ out_mean)
{
    extern __shared__ float sh[];
    float* s_w  = sh;
    float* s_in = sh + CAND_WF;
    int t  = threadIdx.x;
    int b  = blockIdx.z;
    int h0 = blockIdx.y * 16, w0 = blockIdx.x * 32;

    for (int i = t; i < CAND_WF/4; i += 256)
        reinterpret_cast<float4*>(s_w)[i] = make_float4(0.f,0.f,0.f,0.f);
    __syncthreads();
    for (int i = t; i < 18*738; i += 256) {
        int oc = i / 738, k = i % 738;
        s_w[k*COC + oc] = ow[i];
    }

    ull acc[10][2];
    #pragma unroll
    for (int q = 0; q < 10; ++q) { acc[q][0] = 0ULL; acc[q][1] = 0ULL; }

    int ty  = t >> 4;
    int txp = (t & 15) * 2;

    for (int e = t; e < IN_TILE; e += 256) {
        int ch = e / 612; int rr = (e % 612) / 34; int cc2 = e % 34;
        int gh = h0 - 1 + rr, gw = w0 - 1 + cc2;
        float v = 0.f;
        if (gh >= 0 && gh < HH && gw >= 0 && gw < WW)
            v = x[((b*CC + ch)*HH + gh)*WW + gw];
        s_in[e] = v;
    }
    __syncthreads();

    #pragma unroll 1
    for (int it = 0; it < 41; ++it) {
        int c0 = it*2;
        const float* buf = s_in + (it & 1) * IN_TILE;

        float pf[5];
        if (it < 40) {
            int nc0 = c0 + 2;
            #pragma unroll
            for (int s = 0; s < 5; ++s) {
                int e = t + s*256;
                float v = 0.f;
                if (e < IN_TILE) {
                    int ch = e / 612; int rr = (e % 612) / 34; int cc2 = e % 34;
                    int gh = h0 - 1 + rr, gw = w0 - 1 + cc2;
                    if (gh >= 0 && gh < HH && gw >= 0 && gw < WW) {
                        int ic = nc0 + ch;
                        v = (ic < 64) ? x[((b*CC + ic)*HH + gh)*WW + gw]
                                      : g_rgoff[((b*MH + (ic - 64))*HH + gh)*WW + gw];
                    }
                }
                pf[s] = v;
            }
        }

        #pragma unroll
        for (int ch = 0; ch < 2; ++ch) {
            int icb = (c0 + ch)*9;
            #pragma unroll
            for (int ki = 0; ki < 3; ++ki) {
                int ibase = ch*612 + (ty + ki)*34 + txp;
                float2 a0 = *reinterpret_cast<const float2*>(buf + ibase);
                float2 a1 = *reinterpret_cast<const float2*>(buf + ibase + 2);
                ull d0 = dup2(a0.x), d1 = dup2(a0.y), d2 = dup2(a1.x), d3 = dup2(a1.y);
                #pragma unroll
                for (int kj = 0; kj < 3; ++kj) {
                    ull dA = (kj == 0) ? d0 : (kj == 1) ? d1 : d2;
                    ull dB = (kj == 0) ? d1 : (kj == 1) ? d2 : d3;
                    const float* wrow = s_w + (icb + ki*3 + kj)*COC;
                    #pragma unroll
                    for (int q = 0; q < 5; ++q) {
                        ulonglong2 wv = *reinterpret_cast<const ulonglong2*>(wrow + q*4);
                        acc[q*2  ][0] = ffma2(wv.x, dA, acc[q*2  ][0]);
                        acc[q*2  ][1] = ffma2(wv.x, dB, acc[q*2  ][1]);
                        acc[q*2+1][0] = ffma2(wv.y, dA, acc[q*2+1][0]);
                        acc[q*2+1][1] = ffma2(wv.y, dB, acc[q*2+1][1]);
                    }
                }
            }
        }

        if (it < 40) {
            float* nbuf = s_in + ((it + 1) & 1) * IN_TILE;
            #pragma unroll
            for (int s = 0; s < 5; ++s) {
                int e = t + s*256;
                if (e < IN_TILE) nbuf[e] = pf[s];
            }
        }
        __syncthreads();
    }

    int h = h0 + ty;
    int w1 = w0 + txp;
    #pragma unroll
    for (int op = 0; op < 9; ++op) {
        float cA0, cB0, cA1, cB1;
        unpack2(acc[op][0], cA0, cB0);
        unpack2(acc[op][1], cA1, cB1);
        int oc0 = 2*op, oc1 = oc0 + 1;
        #pragma unroll
        for (int s = 0; s < 2; ++s) {
            int oc = s ? oc1 : oc0;
            float c0v = tanhf((s ? cB0 : cA0) + ob[oc]);
            float c1v = tanhf((s ? cB1 : cA1) + ob[oc]);
            int i1 = ((b*MH + oc)*HH + h)*WW + w1;
            float2 u = *reinterpret_cast<const float2*>(g_update + i1);
            float2 p = *reinterpret_cast<const float2*>(pre + i1);
            float2 mn = *reinterpret_cast<const float2*>(mean + i1);
            float mn0 = 0.5f*(mn.x + p.x);
            float mn1 = 0.5f*(mn.y + p.y);
            float2 oo = make_float2(p.x*(1.f - u.x) + c0v*u.x + mn0,
                                    p.y*(1.f - u.y) + c1v*u.y + mn1);
            *reinterpret_cast<float2*>(out_off  + i1) = oo;
            *reinterpret_cast<float2*>(out_mean + i1) = make_float2(mn0, mn1);
        }
    }
}

// ================= deformable warp + regroup conv — f32x2 =================
// smem: WT [576][64] (transposed) + v [64 px][66]
#define WARP_WTF (576*64)
#define WARP_SVP 66
#define WARP_SVF (64*WARP_SVP)
#define WARP_SMEMF (WARP_WTF + WARP_SVF)

__global__ void __launch_bounds__(256, 1) k_warp(
    const float* __restrict__ off, const float* __restrict__ Wc,
    float* __restrict__ out)
{
    extern __shared__ float sh[];
    float* sWT = sh;                  // [k=576][co=64]
    float* sv  = sh + WARP_WTF;       // [pix=64][66]
    int t = threadIdx.x;
    int lane = t & 31, warp = t >> 5;

    for (int i = t; i < 64*576; i += 256) {
        int co = i / 576, k = i % 576;
        sWT[k*64 + co] = Wc[i];
    }
    __syncthreads();

    int c0 = (t & 15) * 2;   // co pair bases: c0, c0+32
    int pg = t >> 4;         // pixel group: px = pg*4 + j

    for (int g = blockIdx.x; g < BB*HH*2; g += gridDim.x) {
        int b = g >> 8;
        int rem = g & 255;
        int h  = rem >> 1;
        int w0 = (rem & 1) << 6;

        ull acc[2][4];
        #pragma unroll
        for (int i = 0; i < 2; ++i)
            #pragma unroll
            for (int j = 0; j < 4; ++j) acc[i][j] = 0ULL;

        #pragma unroll 1
        for (int n = 0; n < 9; ++n) {
            float pnx = (float)(n/3 - 1), pny = (float)(n%3 - 1);
            #pragma unroll 1
            for (int p = 0; p < 8; ++p) {
                int pix = warp*8 + p;
                int wc  = w0 + pix;
                float ox = off[((b*MH + n     )*HH + h)*WW + wc];
                float oy = off[((b*MH + 9 + n )*HH + h)*WW + wc];
                float mm = g_m[((b*NN + n)*HH + h)*WW + wc];
                float px = (float)(h + 1) + pnx + ox;
                float py = (float)(wc + 1) + pny + oy;
                float fx = floorf(px), fy = floorf(py);
                float qxl = fminf(fmaxf(fx,       0.f), 129.f);
                float qxr = fminf(fmaxf(fx + 1.f, 0.f), 129.f);
                float qyl = fminf(fmaxf(fy,       0.f), 129.f);
                float qyr = fminf(fmaxf(fy + 1.f, 0.f), 129.f);
                float pxc = fminf(fmaxf(px, 0.f), 129.f);
                float pyc = fminf(fmaxf(py, 0.f), 129.f);
                float gx_l = 1.f + (qxl - pxc);
                float gx_r = 1.f - (qxr - pxc);
                float gy_l = 1.f + (qyl - pyc);
                float gy_r = 1.f - (qyr - pyc);
                ull glt = dup2(gx_l*gy_l*mm), grb = dup2(gx_r*gy_r*mm);
                ull glb = dup2(gx_l*gy_r*mm), grt = dup2(gx_r*gy_l*mm);
                int ixl = (int)qxl, ixr = (int)qxr, iyl = (int)qyl, iyr = (int)qyr;
                const float* xb = g_xT + b*130*130*64 + 2*lane;
                ull plt = *reinterpret_cast<const ull*>(xb + (ixl*130 + iyl)*64);
                ull prb = *reinterpret_cast<const ull*>(xb + (ixr*130 + iyr)*64);
                ull plb = *reinterpret_cast<const ull*>(xb + (ixl*130 + iyr)*64);
                ull prt = *reinterpret_cast<const ull*>(xb + (ixr*130 + iyl)*64);
                ull v2 = ffma2(grt, prt, ffma2(glb, plb, ffma2(grb, prb, fmul2(glt, plt))));
                *reinterpret_cast<ull*>(sv + pix*WARP_SVP + 2*lane) = v2;
            }
            __syncthreads();
            // acc[cp][j] += W(co pair) * dup(v[px=pg*4+j][ci]) over ci
            #pragma unroll 4
            for (int ci = 0; ci < 64; ++ci) {
                int k = ci*9 + n;
                ull w0p = *reinterpret_cast<const ull*>(sWT + k*64 + c0);
                ull w1p = *reinterpret_cast<const ull*>(sWT + k*64 + c0 + 32);
                #pragma unroll
                for (int j = 0; j < 4; ++j) {
                    ull dv = dup2(sv[(pg*4 + j)*WARP_SVP + ci]);
                    acc[0][j] = ffma2(w0p, dv, acc[0][j]);
                    acc[1][j] = ffma2(w1p, dv, acc[1][j]);
                }
            }
            __syncthreads();
        }

        // stage to smem then coalesced global write
        #pragma unroll
        for (int i = 0; i < 2; ++i) {
            int cb = c0 + i*32;
            #pragma unroll
            for (int j = 0; j < 4; ++j) {
                float lo, hi;
                unpack2(acc[i][j], lo, hi);
                sv[(pg*4 + j)*WARP_SVP + cb]     = lo;
                sv[(pg*4 + j)*WARP_SVP + cb + 1] = hi;
            }
        }
        __syncthreads();
        for (int i = t; i < 4096; i += 256) {
            int co = i >> 6, pix = i & 63;
            out[((b*CC + co)*HH + h)*WW + w0 + pix] = sv[pix*WARP_SVP + co];
        }
        __syncthreads();
    }
}

// ---------------- launch ----------------
extern "C" void kernel_launch(void* const* d_in, const int* in_sizes, int n_in,
                              void* d_out, int out_size)
{
    const float* x    = (const float*)d_in[0];
    const float* pre  = (const float*)d_in[1];
    const float* mean = (const float*)d_in[2];
    const float* uw   = (const float*)d_in[3];
    const float* ub   = (const float*)d_in[4];
    const float* rw   = (const float*)d_in[5];
    const float* rb   = (const float*)d_in[6];
    const float* ow   = (const float*)d_in[7];
    const float* ob   = (const float*)d_in[8];
    const float* ww   = (const float*)d_in[9];
    const float* wb   = (const float*)d_in[10];
    const float* wc   = (const float*)d_in[11];

    float* out_x    = (float*)d_out;
    float* out_off  = out_x + BB*CC*HH*WW;
    float* out_mean = out_off + BB*MH*HH*WW;

    cudaFuncSetAttribute(k_gatesm, cudaFuncAttributeMaxDynamicSharedMemorySize,
                         GATE_SMEMF * (int)sizeof(float));
    cudaFuncSetAttribute(k_cand, cudaFuncAttributeMaxDynamicSharedMemorySize,
                         CAND_SMEMF * (int)sizeof(float));
    cudaFuncSetAttribute(k_warp, cudaFuncAttributeMaxDynamicSharedMemorySize,
                         WARP_SMEMF * (int)sizeof(float));

    k_zero<<<(BB*130*130*CC/4 + 255)/256, 256>>>();
    k_pad<<<dim3(4, 128, 4), dim3(32, 8)>>>(x);

    dim3 gg(WW/32, HH/16, BB);
    k_gatesm<<<gg, 256, GATE_SMEMF * sizeof(float)>>>(x, pre, uw, ub, rw, rb, ww, wb);
    k_cand<<<gg, 256, CAND_SMEMF * sizeof(float)>>>(x, pre, mean, ow, ob, out_off, out_mean);
    k_warp<<<148, 256, WARP_SMEMF * sizeof(float)>>>(out_off, wc, out_x);
}